// round 2
// baseline (speedup 1.0000x reference)
#include <cuda_runtime.h>

typedef unsigned long long ull;

// ---------------- scratch (device globals; allocation-free) ----------------
__device__ float g_hA[16384*256];
__device__ float g_hB[16384*256];
__device__ float g_c [16384*256];
__device__ float g_childA[16384*256];
__device__ float g_childB[4096*256];
__device__ float g_WcatT[512*1024];     // [k][jj*4+g]  (k<256: W_ih part, else W_hh)
__device__ float g_Wcomb[256*512];      // Wt @ Wc, row-major [i][k]
__device__ float g_WcombHT[256*256];    // transposed h-half: [k][i]
__device__ float g_bcomb[256];
__device__ float g_tagE[26*256];
__device__ float g_leafout[26*256];
__device__ float g_leafxW[26*1024];     // [v][jj*4+g], biases folded in
__device__ float g_h1[256];
__device__ float g_c1[256];
__device__ float g_bzT[1024];           // [jj*4+g] = b_ih+b_hh reordered

__device__ __forceinline__ float sigm(float x){ return 1.0f/(1.0f+expf(-x)); }

__device__ __forceinline__ ull fma2(ull a, ull b, ull c){
    ull d;
    asm("fma.rn.f32x2 %0, %1, %2, %3;" : "=l"(d) : "l"(a), "l"(b), "l"(c));
    return d;
}
__device__ __forceinline__ float2 unpk(ull v){
    float2 r;
    asm("mov.b64 {%0, %1}, %2;" : "=f"(r.x), "=f"(r.y) : "l"(v));
    return r;
}

// ---------------- prologue kernels ----------------
__global__ void k_init_h1c1(const float* __restrict__ W_ih, const float* __restrict__ b_ih,
                            const float* __restrict__ b_hh, const float* __restrict__ lstm_init)
{
    __shared__ float xs[256];
    __shared__ float z[1024];
    int j = threadIdx.x;
    if (j < 256) xs[j] = lstm_init[j];
    __syncthreads();
    float s = b_ih[j] + b_hh[j];
    const float* w = &W_ih[j*256];
    #pragma unroll 8
    for (int k = 0; k < 256; k++) s += xs[k]*w[k];
    z[j] = s;
    __syncthreads();
    if (j < 256){
        float c = sigm(z[j]) * tanhf(z[j+512]);     // sig(i)*tanh(g), c0=0
        g_c1[j] = c;
        g_h1[j] = sigm(z[j+768]) * tanhf(c);
    }
}

__global__ void k_build_wcatT(const float* __restrict__ W_ih, const float* __restrict__ W_hh)
{
    int idx = blockIdx.x*256 + threadIdx.x;  // 0..524287
    int k = idx >> 10, col = idx & 1023;
    int jj = col >> 2, g = col & 3;
    int row = g*256 + jj;
    g_WcatT[idx] = (k < 256) ? W_ih[row*256 + k] : W_hh[row*256 + (k-256)];
}

__global__ void k_bzT(const float* __restrict__ b_ih, const float* __restrict__ b_hh)
{
    int idx = threadIdx.x;               // 0..1023
    int jj = idx >> 2, g = idx & 3;
    g_bzT[idx] = b_ih[g*256+jj] + b_hh[g*256+jj];
}

__global__ void k_wcomb(const float* __restrict__ Wt, const float* __restrict__ Wc)
{
    int idx = blockIdx.x*256 + threadIdx.x;   // 0..131071
    int i = idx >> 9, k = idx & 511;
    float s = 0.f;
    #pragma unroll 8
    for (int j = 0; j < 256; j++) s += Wt[i*256+j]*Wc[j*512+k];
    g_Wcomb[idx] = s;
}

__global__ void k_bcomb(const float* __restrict__ Wt, const float* __restrict__ bc,
                        const float* __restrict__ bt)
{
    int i = threadIdx.x;
    float s = bt[i];
    #pragma unroll 8
    for (int j = 0; j < 256; j++) s += Wt[i*256+j]*bc[j];
    g_bcomb[i] = s;
}

__global__ void k_wcombHT()
{
    int idx = blockIdx.x*256 + threadIdx.x;   // [k][i]
    int k = idx >> 8, i = idx & 255;
    g_WcombHT[idx] = g_Wcomb[i*512 + k];
}

__global__ void k_tagE(const float* __restrict__ emb)
{
    int v = blockIdx.x, i = threadIdx.x;
    __shared__ float es[256];
    es[i] = emb[v*256 + i];
    __syncthreads();
    float s = 0.f;
    #pragma unroll 8
    for (int k = 0; k < 256; k++) s += es[k]*g_Wcomb[i*512 + 256 + k];
    g_tagE[v*256 + i] = s;
}

__global__ void k_leafout()
{
    int v = blockIdx.x, i = threadIdx.x;
    __shared__ float h1s[256];
    __shared__ float red[256];
    h1s[i] = g_h1[i];
    __syncthreads();
    float s = g_tagE[v*256+i] + g_bcomb[i];
    #pragma unroll 8
    for (int k = 0; k < 256; k++) s += h1s[k]*g_Wcomb[i*512 + k];
    red[i] = s; __syncthreads();
    for (int st = 128; st > 0; st >>= 1){ if (i < st) red[i] = fmaxf(red[i], red[i+st]); __syncthreads(); }
    float mx = red[0]; __syncthreads();
    red[i] = expf(s - mx); __syncthreads();
    for (int st = 128; st > 0; st >>= 1){ if (i < st) red[i] += red[i+st]; __syncthreads(); }
    float lse = mx + logf(red[0]);
    g_leafout[v*256 + i] = s - lse;
}

__global__ void k_leafxw(const float* __restrict__ W_ih, const float* __restrict__ b_ih,
                         const float* __restrict__ b_hh)
{
    int blk = blockIdx.x;           // 0..103 = v*4 + jb
    int v = blk >> 2, jb = blk & 3;
    int c = jb*256 + threadIdx.x;   // 0..1023 (layout [jj*4+g])
    int jj = c >> 2, g = c & 3;
    int row = g*256 + jj;
    __shared__ float lo[256];
    lo[threadIdx.x] = g_leafout[v*256 + threadIdx.x];
    __syncthreads();
    float s = b_ih[row] + b_hh[row];
    #pragma unroll 8
    for (int k = 0; k < 256; k++) s += lo[k]*W_ih[row*256 + k];
    g_leafxW[v*1024 + c] = s;
}

// ---------------- fused LSTM step v2: f32x2 packed FMA ----------------
// MODE 0: level 7. K=256 (h only), x-contribution from g_leafxW gather.
// MODE 1: levels <=6. K=512, A = [x ; h].
// Block: BM rows x 128 cols (32 jj x 4 gates). 256 threads.
// Thread tile: TM=BM/16 rows x 8 cols (= 4 f32x2 j-pairs).
// A stored duplicated {a,a} in smem so one ulonglong2 = 2 broadcast pairs.
template<int MODE, int BM>
__global__ void __launch_bounds__(256, 2)
step2_kernel(const float* __restrict__ hin, float* __restrict__ hout,
             float* __restrict__ cbuf,
             const float* __restrict__ WT,        // [k][jj*4+g]
             const float* __restrict__ x,         // MODE1 child buf
             const int*   __restrict__ ids,       // MODE0: idents+leafoff+t
             const float* __restrict__ leafxW,    // MODE0
             const float* __restrict__ bzT,       // MODE1
             const float* __restrict__ c1,
             int t, int first, int M)
{
    const int KD = (MODE == 0) ? 256 : 512;
    const int KT = 16;
    const int TM = BM/16;
    __shared__ float As[KT][2*BM];     // duplicated pairs
    __shared__ float Ws[KT][132];      // 128 cols + pad

    int tid = threadIdx.x;
    int tj = tid & 15;                 // col group: cols j0 + tj*8 .. +7
    int tm = tid >> 4;                 // row group: rows m0 + tm*TM .. +TM-1
    int m0 = blockIdx.x * BM;
    int j0 = blockIdx.y * 128;

    ull acc[TM][4];
    #pragma unroll
    for (int a = 0; a < TM; a++)
        #pragma unroll
        for (int b = 0; b < 4; b++) acc[a][b] = 0ull;

    for (int k0 = 0; k0 < KD; k0 += KT){
        // fill A (duplicated)
        const int AV = KT*BM/256;
        #pragma unroll
        for (int q = 0; q < AV; q++){
            int e = tid + q*256;
            int kk = e & 15, m = e >> 4;
            int gm = m0 + m;
            float v = 0.f;
            if (gm < M){
                int k = k0 + kk;
                if (MODE == 0){
                    v = first ? hin[k] : hin[gm*256 + k];
                } else {
                    if (k < 256) v = x[(gm*4 + t)*256 + k];
                    else         v = first ? hin[k-256] : hin[gm*256 + (k-256)];
                }
            }
            *reinterpret_cast<float2*>(&As[kk][2*m]) = make_float2(v, v);
        }
        // fill W tile: 16 k x 128 cols
        #pragma unroll
        for (int q = 0; q < 2; q++){
            int e = tid + q*256;
            int kk = e >> 5, c4 = e & 31;
            *reinterpret_cast<float4*>(&Ws[kk][c4*4]) =
                *reinterpret_cast<const float4*>(&WT[(k0+kk)*1024 + j0 + c4*4]);
        }
        __syncthreads();
        #pragma unroll
        for (int kk = 0; kk < KT; kk++){
            ulonglong2 b01 = *reinterpret_cast<const ulonglong2*>(&Ws[kk][tj*8]);
            ulonglong2 b23 = *reinterpret_cast<const ulonglong2*>(&Ws[kk][tj*8+4]);
            #pragma unroll
            for (int p = 0; p < TM/2; p++){
                ulonglong2 a2 = *reinterpret_cast<const ulonglong2*>(&As[kk][2*(tm*TM + 2*p)]);
                acc[2*p  ][0] = fma2(a2.x, b01.x, acc[2*p  ][0]);
                acc[2*p  ][1] = fma2(a2.x, b01.y, acc[2*p  ][1]);
                acc[2*p  ][2] = fma2(a2.x, b23.x, acc[2*p  ][2]);
                acc[2*p  ][3] = fma2(a2.x, b23.y, acc[2*p  ][3]);
                acc[2*p+1][0] = fma2(a2.y, b01.x, acc[2*p+1][0]);
                acc[2*p+1][1] = fma2(a2.y, b01.y, acc[2*p+1][1]);
                acc[2*p+1][2] = fma2(a2.y, b23.x, acc[2*p+1][2]);
                acc[2*p+1][3] = fma2(a2.y, b23.y, acc[2*p+1][3]);
            }
        }
        __syncthreads();
    }

    // epilogue: thread owns gate-quads jja, jja+1 for TM rows
    int jja = (j0 >> 2) + tj*2;
    float4 addA, addB;
    if (MODE == 1){
        addA = *reinterpret_cast<const float4*>(&bzT[jja*4]);
        addB = *reinterpret_cast<const float4*>(&bzT[(jja+1)*4]);
    }
    float c1a = first ? c1[jja] : 0.f;
    float c1b = first ? c1[jja+1] : 0.f;

    #pragma unroll
    for (int mi = 0; mi < TM; mi++){
        int gm = m0 + tm*TM + mi;
        if (gm >= M) continue;
        if (MODE == 0){
            int id = ids[gm*4];
            addA = *reinterpret_cast<const float4*>(&leafxW[id*1024 + jja*4]);
            addB = *reinterpret_cast<const float4*>(&leafxW[id*1024 + (jja+1)*4]);
        }
        float2 p0 = unpk(acc[mi][0]);
        float2 p1 = unpk(acc[mi][1]);
        float2 p2 = unpk(acc[mi][2]);
        float2 p3 = unpk(acc[mi][3]);
        // quad A
        {
            float zi = p0.x + addA.x, zf = p0.y + addA.y;
            float zg = p1.x + addA.z, zo = p1.y + addA.w;
            float cold = first ? c1a : cbuf[gm*256 + jja];
            float cn = sigm(zf)*cold + sigm(zi)*tanhf(zg);
            cbuf[gm*256 + jja] = cn;
            hout[gm*256 + jja] = sigm(zo)*tanhf(cn);
        }
        // quad B
        {
            float zi = p2.x + addB.x, zf = p2.y + addB.y;
            float zg = p3.x + addB.z, zo = p3.y + addB.w;
            float cold = first ? c1b : cbuf[gm*256 + jja + 1];
            float cn = sigm(zf)*cold + sigm(zi)*tanhf(zg);
            cbuf[gm*256 + jja + 1] = cn;
            hout[gm*256 + jja + 1] = sigm(zo)*tanhf(cn);
        }
    }
}

// ---------------- tag + log_softmax ----------------
__global__ void tag_kernel(const float* __restrict__ h, const int* __restrict__ ids,
                           float* __restrict__ out, int M)
{
    __shared__ float As[32][20];
    __shared__ float Ws[32][256];
    __shared__ float red[16][16];
    __shared__ float rowmax[16], rowlse[16];
    float* stag = &Ws[0][0];

    int tid = threadIdx.x;
    int rg = tid >> 6;
    int cg = tid & 63;
    int m0 = blockIdx.x * 16;

    float acc[4][4];
    #pragma unroll
    for (int a = 0; a < 4; a++)
        #pragma unroll
        for (int b = 0; b < 4; b++) acc[a][b] = 0.f;

    for (int k0 = 0; k0 < 256; k0 += 32){
        #pragma unroll
        for (int q = 0; q < 2; q++){
            int e = tid + q*256;
            int m = e >> 5, kk = e & 31;
            int gm = m0 + m;
            As[kk][m] = (gm < M) ? h[gm*256 + k0 + kk] : 0.f;
        }
        #pragma unroll
        for (int q = 0; q < 8; q++){
            int e = tid + q*256;
            int kk = e >> 6, c4 = e & 63;
            *reinterpret_cast<float4*>(&Ws[kk][c4*4]) =
                *reinterpret_cast<const float4*>(&g_WcombHT[(k0+kk)*256 + c4*4]);
        }
        __syncthreads();
        #pragma unroll
        for (int kk = 0; kk < 32; kk++){
            float4 a = *reinterpret_cast<const float4*>(&As[kk][rg*4]);
            float4 b = *reinterpret_cast<const float4*>(&Ws[kk][cg*4]);
            acc[0][0] = fmaf(a.x, b.x, acc[0][0]); acc[0][1] = fmaf(a.x, b.y, acc[0][1]);
            acc[0][2] = fmaf(a.x, b.z, acc[0][2]); acc[0][3] = fmaf(a.x, b.w, acc[0][3]);
            acc[1][0] = fmaf(a.y, b.x, acc[1][0]); acc[1][1] = fmaf(a.y, b.y, acc[1][1]);
            acc[1][2] = fmaf(a.y, b.z, acc[1][2]); acc[1][3] = fmaf(a.y, b.w, acc[1][3]);
            acc[2][0] = fmaf(a.z, b.x, acc[2][0]); acc[2][1] = fmaf(a.z, b.y, acc[2][1]);
            acc[2][2] = fmaf(a.z, b.z, acc[2][2]); acc[2][3] = fmaf(a.z, b.w, acc[2][3]);
            acc[3][0] = fmaf(a.w, b.x, acc[3][0]); acc[3][1] = fmaf(a.w, b.y, acc[3][1]);
            acc[3][2] = fmaf(a.w, b.z, acc[3][2]); acc[3][3] = fmaf(a.w, b.w, acc[3][3]);
        }
        __syncthreads();
    }

    float4 bc = *reinterpret_cast<const float4*>(&g_bcomb[cg*4]);
    #pragma unroll
    for (int ri = 0; ri < 4; ri++){
        int r = rg*4 + ri;
        int gm = m0 + r;
        int id = (gm < M) ? ids[gm] : 0;
        float4 te = *reinterpret_cast<const float4*>(&g_tagE[id*256 + cg*4]);
        float4 v = make_float4(acc[ri][0]+te.x+bc.x, acc[ri][1]+te.y+bc.y,
                               acc[ri][2]+te.z+bc.z, acc[ri][3]+te.w+bc.w);
        *reinterpret_cast<float4*>(&stag[r*256 + cg*4]) = v;
    }
    __syncthreads();
    {
        int r = tid >> 4, s = tid & 15;
        float mx = -1e30f;
        #pragma unroll
        for (int q = 0; q < 16; q++) mx = fmaxf(mx, stag[r*256 + s*16 + q]);
        red[r][s] = mx;
    }
    __syncthreads();
    if (tid < 16){
        float mx = red[tid][0];
        #pragma unroll
        for (int s = 1; s < 16; s++) mx = fmaxf(mx, red[tid][s]);
        rowmax[tid] = mx;
    }
    __syncthreads();
    {
        int r = tid >> 4, s = tid & 15;
        float sm = 0.f, mx = rowmax[r];
        #pragma unroll
        for (int q = 0; q < 16; q++) sm += expf(stag[r*256 + s*16 + q] - mx);
        red[r][s] = sm;
    }
    __syncthreads();
    if (tid < 16){
        float sm = 0.f;
        #pragma unroll
        for (int s = 0; s < 16; s++) sm += red[tid][s];
        rowlse[tid] = logf(sm);
    }
    __syncthreads();
    #pragma unroll
    for (int q = 0; q < 16; q++){
        int e = tid + q*256;
        int r = e >> 8, i = e & 255;
        int gm = m0 + r;
        if (gm < M) out[gm*256 + i] = stag[r*256 + i] - rowmax[r] - rowlse[r];
    }
}

// ---------------- host launcher ----------------
extern "C" void kernel_launch(void* const* d_in, const int* in_sizes, int n_in,
                              void* d_out, int out_size)
{
    const int*   idents    = (const int*)  d_in[0];
    const float* emb       = (const float*)d_in[1];
    const float* W_ih      = (const float*)d_in[2];
    const float* W_hh      = (const float*)d_in[3];
    const float* b_ih      = (const float*)d_in[4];
    const float* b_hh      = (const float*)d_in[5];
    const float* Wc        = (const float*)d_in[6];
    const float* bc        = (const float*)d_in[7];
    const float* Wt        = (const float*)d_in[8];
    const float* bt        = (const float*)d_in[9];
    const float* lstm_init = (const float*)d_in[10];
    float* out = (float*)d_out;
    (void)in_sizes; (void)n_in; (void)out_size;

    void* p;
    float *hA, *hB, *cbuf, *chA, *chB, *wcatT, *leafxW, *bzT, *h1, *c1;
    cudaGetSymbolAddress(&p, g_hA);     hA     = (float*)p;
    cudaGetSymbolAddress(&p, g_hB);     hB     = (float*)p;
    cudaGetSymbolAddress(&p, g_c);      cbuf   = (float*)p;
    cudaGetSymbolAddress(&p, g_childA); chA    = (float*)p;
    cudaGetSymbolAddress(&p, g_childB); chB    = (float*)p;
    cudaGetSymbolAddress(&p, g_WcatT);  wcatT  = (float*)p;
    cudaGetSymbolAddress(&p, g_leafxW); leafxW = (float*)p;
    cudaGetSymbolAddress(&p, g_bzT);    bzT    = (float*)p;
    cudaGetSymbolAddress(&p, g_h1);     h1     = (float*)p;
    cudaGetSymbolAddress(&p, g_c1);     c1     = (float*)p;
    float* hbuf[2]  = { hA, hB };
    float* child[2] = { chA, chB };

    // prologue (tiny)
    k_init_h1c1<<<1, 1024>>>(W_ih, b_ih, b_hh, lstm_init);
    k_build_wcatT<<<2048, 256>>>(W_ih, W_hh);
    k_bzT<<<1, 1024>>>(b_ih, b_hh);
    k_wcomb<<<512, 256>>>(Wt, Wc);
    k_bcomb<<<1, 256>>>(Wt, bc, bt);
    k_wcombHT<<<256, 256>>>();
    k_tagE<<<26, 256>>>(emb);
    k_leafout<<<26, 256>>>();
    k_leafxw<<<104, 256>>>(W_ih, b_ih, b_hh);

    // level 7 (leaf children come from the 26-entry precomputed table)
    {
        int M = 16384;
        const int leaf_off = 21845;   // (4^8-1)/3
        const int off7 = 5461;        // (4^7-1)/3
        dim3 grid(M/128, 8);
        for (int t = 0; t < 4; t++){
            const float* hin = (t == 0) ? h1 : hbuf[(t+1)&1];
            step2_kernel<0,128><<<grid, 256>>>(hin, hbuf[t&1], cbuf,
                                               wcatT + 256*1024,   // W_hh^T portion
                                               nullptr, idents + leaf_off + t,
                                               leafxW, nullptr, c1, t, (t==0)?1:0, M);
        }
        tag_kernel<<<(M + 15)/16, 256>>>(hbuf[1], idents + off7, child[0], M);
    }

    // levels 6..0
    int cur = 0;  // child[cur] holds child_out of level l+1
    for (int l = 6; l >= 0; l--){
        int M = 1 << (2*l);
        int off = (M - 1)/3;
        for (int t = 0; t < 4; t++){
            const float* hin = (t == 0) ? h1 : hbuf[(t+1)&1];
            if (M >= 2048){
                dim3 grid(M/128, 8);
                step2_kernel<1,128><<<grid, 256>>>(hin, hbuf[t&1], cbuf,
                                                   wcatT, child[cur], nullptr,
                                                   nullptr, bzT, c1, t, (t==0)?1:0, M);
            } else {
                dim3 grid((M + 31)/32, 8);
                step2_kernel<1,32><<<grid, 256>>>(hin, hbuf[t&1], cbuf,
                                                  wcatT, child[cur], nullptr,
                                                  nullptr, bzT, c1, t, (t==0)?1:0, M);
            }
        }
        float* o = (l == 0) ? out : child[cur ^ 1];
        tag_kernel<<<(M + 15)/16, 256>>>(hbuf[1], idents + off, o, M);
        cur ^= 1;
    }
}

// round 3
// speedup vs baseline: 1.4753x; 1.4753x over previous
#include <cuda_runtime.h>

// ---------------- scratch (device globals; allocation-free) ----------------
__device__ float g_hA[16384*256];
__device__ float g_hB[16384*256];
__device__ float g_c [16384*256];
__device__ float g_childA[16384*256];
__device__ float g_childB[4096*256];
__device__ float g_xw[16384*1024];      // x@W_ih^T + biases, per child row, layout [m][jj*4+g]
__device__ float g_WcatT[512*1024];     // [k][jj*4+g]  (k<256: W_ih part, else W_hh)
__device__ float g_Wcomb[256*512];      // Wt @ Wc, row-major [i][k]
__device__ float g_WcombHT[256*256];    // transposed h-half: [k][i]
__device__ float g_bcomb[256];
__device__ float g_tagE[26*256];
__device__ float g_leafout[26*256];
__device__ float g_leafxW[26*1024];     // [v][jj*4+g], biases folded in
__device__ float g_h1[256];
__device__ float g_c1[256];
__device__ float g_bzT[1024];           // [jj*4+g] = b_ih+b_hh reordered
__device__ float g_hh1[1024];           // W_hh^T-proj of h1, layout [jj*4+g]
__device__ float g_h26[26*256];
__device__ float g_c26[26*256];
__device__ float g_h676[676*256];
__device__ float g_c676[676*256];

__device__ __forceinline__ float sigm(float x){ return 1.0f/(1.0f+expf(-x)); }

// ---------------- prologue kernels ----------------
__global__ void k_init_h1c1(const float* __restrict__ W_ih, const float* __restrict__ b_ih,
                            const float* __restrict__ b_hh, const float* __restrict__ lstm_init)
{
    __shared__ float xs[256];
    __shared__ float z[1024];
    int j = threadIdx.x;
    if (j < 256) xs[j] = lstm_init[j];
    __syncthreads();
    float s = b_ih[j] + b_hh[j];
    const float* w = &W_ih[j*256];
    #pragma unroll 8
    for (int k = 0; k < 256; k++) s += xs[k]*w[k];
    z[j] = s;
    __syncthreads();
    if (j < 256){
        float c = sigm(z[j]) * tanhf(z[j+512]);     // sig(i)*tanh(g), c0=0
        g_c1[j] = c;
        g_h1[j] = sigm(z[j+768]) * tanhf(c);
    }
}

__global__ void k_build_wcatT(const float* __restrict__ W_ih, const float* __restrict__ W_hh)
{
    int idx = blockIdx.x*256 + threadIdx.x;  // 0..524287
    int k = idx >> 10, col = idx & 1023;
    int jj = col >> 2, g = col & 3;
    int row = g*256 + jj;
    g_WcatT[idx] = (k < 256) ? W_ih[row*256 + k] : W_hh[row*256 + (k-256)];
}

__global__ void k_bzT(const float* __restrict__ b_ih, const float* __restrict__ b_hh)
{
    int idx = threadIdx.x;               // 0..1023
    int jj = idx >> 2, g = idx & 3;
    g_bzT[idx] = b_ih[g*256+jj] + b_hh[g*256+jj];
}

__global__ void k_wcomb(const float* __restrict__ Wt, const float* __restrict__ Wc)
{
    int idx = blockIdx.x*256 + threadIdx.x;   // 0..131071
    int i = idx >> 9, k = idx & 511;
    float s = 0.f;
    #pragma unroll 8
    for (int j = 0; j < 256; j++) s += Wt[i*256+j]*Wc[j*512+k];
    g_Wcomb[idx] = s;
}

__global__ void k_bcomb(const float* __restrict__ Wt, const float* __restrict__ bc,
                        const float* __restrict__ bt)
{
    int i = threadIdx.x;
    float s = bt[i];
    #pragma unroll 8
    for (int j = 0; j < 256; j++) s += Wt[i*256+j]*bc[j];
    g_bcomb[i] = s;
}

__global__ void k_wcombHT()
{
    int idx = blockIdx.x*256 + threadIdx.x;   // [k][i]
    int k = idx >> 8, i = idx & 255;
    g_WcombHT[idx] = g_Wcomb[i*512 + k];
}

__global__ void k_tagE(const float* __restrict__ emb)
{
    int v = blockIdx.x, i = threadIdx.x;
    __shared__ float es[256];
    es[i] = emb[v*256 + i];
    __syncthreads();
    float s = 0.f;
    #pragma unroll 8
    for (int k = 0; k < 256; k++) s += es[k]*g_Wcomb[i*512 + 256 + k];
    g_tagE[v*256 + i] = s;
}

__global__ void k_leafout()
{
    int v = blockIdx.x, i = threadIdx.x;
    __shared__ float h1s[256];
    __shared__ float red[256];
    h1s[i] = g_h1[i];
    __syncthreads();
    float s = g_tagE[v*256+i] + g_bcomb[i];
    #pragma unroll 8
    for (int k = 0; k < 256; k++) s += h1s[k]*g_Wcomb[i*512 + k];
    red[i] = s; __syncthreads();
    for (int st = 128; st > 0; st >>= 1){ if (i < st) red[i] = fmaxf(red[i], red[i+st]); __syncthreads(); }
    float mx = red[0]; __syncthreads();
    red[i] = expf(s - mx); __syncthreads();
    for (int st = 128; st > 0; st >>= 1){ if (i < st) red[i] += red[i+st]; __syncthreads(); }
    float lse = mx + logf(red[0]);
    g_leafout[v*256 + i] = s - lse;
}

__global__ void k_leafxw(const float* __restrict__ W_ih, const float* __restrict__ b_ih,
                         const float* __restrict__ b_hh)
{
    int blk = blockIdx.x;           // 0..103 = v*4 + jb
    int v = blk >> 2, jb = blk & 3;
    int c = jb*256 + threadIdx.x;   // 0..1023 (layout [jj*4+g])
    int jj = c >> 2, g = c & 3;
    int row = g*256 + jj;
    __shared__ float lo[256];
    lo[threadIdx.x] = g_leafout[v*256 + threadIdx.x];
    __syncthreads();
    float s = b_ih[row] + b_hh[row];
    #pragma unroll 8
    for (int k = 0; k < 256; k++) s += lo[k]*W_ih[row*256 + k];
    g_leafxW[v*1024 + c] = s;
}

// hh1[col] = sum_k h1[k] * WhhT[k*1024+col]
__global__ void k_hh1()
{
    __shared__ float h1s[256];
    int col = blockIdx.x*256 + threadIdx.x;
    if (threadIdx.x < 256) h1s[threadIdx.x] = g_h1[threadIdx.x];
    __syncthreads();
    const float* w = g_WcatT + 256*1024;
    float s = 0.f;
    #pragma unroll 8
    for (int k = 0; k < 256; k++) s += h1s[k]*w[k*1024 + col];
    g_hh1[col] = s;
}

// 26 states after leaf child-step 0: z = hh1 + leafxW[v]; cell from (h1,c1)
__global__ void k_cell26()
{
    int v = blockIdx.x, j = threadIdx.x;
    float4 zh = *reinterpret_cast<const float4*>(&g_hh1[j*4]);
    float4 zl = *reinterpret_cast<const float4*>(&g_leafxW[v*1024 + j*4]);
    float zi = zh.x + zl.x, zf = zh.y + zl.y, zg = zh.z + zl.z, zo = zh.w + zl.w;
    float cn = sigm(zf)*g_c1[j] + sigm(zi)*tanhf(zg);
    g_c26[v*256 + j] = cn;
    g_h26[v*256 + j] = sigm(zo)*tanhf(cn);
}

// ---------------- unified GEMM kernels ----------------
// MODE 0: xw = x @ W_ih^T + bzT         (hin=x rows, hout=xw out)
// MODE 1: LSTM step, add = addbase[(gm*4)]  (addbase pre-offset by t*1024)
// MODE 2: LSTM step, add = leafxW[ids[gm*4]]
// MODE 3: LSTM step pairs: A row = gm/26, add = leafxW[gm%26]
// MODE 4: LSTM step triples: A row = id0*26+id1, add = leafxW[id2]
// c read from cin[rsrc], write cout[gm]; h write hout[gm]. K=256 always.

template<int MODE>
__global__ void __launch_bounds__(256)
gemm_big(const float* __restrict__ hin, float* __restrict__ hout,
         const float* __restrict__ cin, float* __restrict__ cout,
         const float* __restrict__ WT,
         const int* __restrict__ ids,
         const float* __restrict__ addbase,
         const float* __restrict__ c1,
         int first, int M)
{
    __shared__ float As[16*132];
    __shared__ float Ws[16*128];
    __shared__ int rmap[128];
    __shared__ int aidx[128];

    int tid = threadIdx.x;
    int tj = tid & 15;
    int tm = tid >> 4;
    int m0 = blockIdx.x * 128;
    int j0q = blockIdx.y * 32;      // quad base

    if (tid < 128){
        int gm = m0 + tid;
        int r = 0, a = 0;
        if (gm < M){
            if (MODE == 0){ r = gm; }
            else if (MODE == 1){ r = gm; a = gm*4; }
            else if (MODE == 2){ r = gm; a = ids[gm*4]; }
            else if (MODE == 3){ r = gm/26; a = gm - r*26; }
            else { int i0 = ids[gm*4], i1 = ids[gm*4+1]; a = ids[gm*4+2]; r = i0*26 + i1; }
        }
        rmap[tid] = r; aidx[tid] = a;
    }
    __syncthreads();

    float acc[2][2][4][4];
    #pragma unroll
    for (int a = 0; a < 2; a++) for (int b = 0; b < 2; b++)
        #pragma unroll
        for (int c = 0; c < 4; c++) for (int d = 0; d < 4; d++) acc[a][b][c][d] = 0.f;

    for (int k0 = 0; k0 < 256; k0 += 16){
        #pragma unroll
        for (int q = 0; q < 8; q++){
            int e = tid + q*256;
            int kk = e & 15, m = e >> 4;
            int gm = m0 + m;
            float v = 0.f;
            if (gm < M){
                int k = k0 + kk;
                v = (MODE != 0 && first) ? hin[k] : hin[rmap[m]*256 + k];
            }
            As[kk*132 + m] = v;
        }
        #pragma unroll
        for (int q = 0; q < 2; q++){
            int e = tid + q*256;
            int kk = e >> 5, c4 = e & 31;
            *reinterpret_cast<float4*>(&Ws[kk*128 + c4*4]) =
                *reinterpret_cast<const float4*>(&WT[(k0+kk)*1024 + j0q*4 + c4*4]);
        }
        __syncthreads();
        #pragma unroll
        for (int kk = 0; kk < 16; kk++){
            float4 a0 = *reinterpret_cast<const float4*>(&As[kk*132 + tm*4]);
            float4 a1 = *reinterpret_cast<const float4*>(&As[kk*132 + 64 + tm*4]);
            float4 b0 = *reinterpret_cast<const float4*>(&Ws[kk*128 + tj*4]);
            float4 b1 = *reinterpret_cast<const float4*>(&Ws[kk*128 + 64 + tj*4]);
            float ar[2][4] = {{a0.x,a0.y,a0.z,a0.w},{a1.x,a1.y,a1.z,a1.w}};
            float br[2][4] = {{b0.x,b0.y,b0.z,b0.w},{b1.x,b1.y,b1.z,b1.w}};
            #pragma unroll
            for (int rh = 0; rh < 2; rh++)
                #pragma unroll
                for (int ri = 0; ri < 4; ri++)
                    #pragma unroll
                    for (int ch = 0; ch < 2; ch++)
                        #pragma unroll
                        for (int ci = 0; ci < 4; ci++)
                            acc[rh][ch][ri][ci] = fmaf(ar[rh][ri], br[ch][ci], acc[rh][ch][ri][ci]);
        }
        __syncthreads();
    }

    int q0 = j0q + tj, q1 = j0q + tj + 16;
    if (MODE == 0){
        float4 bz0 = *reinterpret_cast<const float4*>(&addbase[q0*4]);
        float4 bz1 = *reinterpret_cast<const float4*>(&addbase[q1*4]);
        #pragma unroll
        for (int rh = 0; rh < 2; rh++)
            #pragma unroll
            for (int ri = 0; ri < 4; ri++){
                int gm = m0 + rh*64 + tm*4 + ri;
                if (gm >= M) continue;
                float4 v0 = make_float4(acc[rh][0][ri][0]+bz0.x, acc[rh][0][ri][1]+bz0.y,
                                        acc[rh][0][ri][2]+bz0.z, acc[rh][0][ri][3]+bz0.w);
                float4 v1 = make_float4(acc[rh][1][ri][0]+bz1.x, acc[rh][1][ri][1]+bz1.y,
                                        acc[rh][1][ri][2]+bz1.z, acc[rh][1][ri][3]+bz1.w);
                *reinterpret_cast<float4*>(&hout[gm*1024 + q0*4]) = v0;
                *reinterpret_cast<float4*>(&hout[gm*1024 + q1*4]) = v1;
            }
    } else {
        float cA = first ? c1[q0] : 0.f;
        float cB = first ? c1[q1] : 0.f;
        #pragma unroll
        for (int rh = 0; rh < 2; rh++)
            #pragma unroll
            for (int ri = 0; ri < 4; ri++){
                int m = rh*64 + tm*4 + ri;
                int gm = m0 + m;
                if (gm >= M) continue;
                const float* ad = addbase + aidx[m]*1024;
                float4 a0 = *reinterpret_cast<const float4*>(&ad[q0*4]);
                float4 a1 = *reinterpret_cast<const float4*>(&ad[q1*4]);
                {
                    float zi = acc[rh][0][ri][0]+a0.x, zf = acc[rh][0][ri][1]+a0.y;
                    float zg = acc[rh][0][ri][2]+a0.z, zo = acc[rh][0][ri][3]+a0.w;
                    float cold = first ? cA : cin[rmap[m]*256 + q0];
                    float cn = sigm(zf)*cold + sigm(zi)*tanhf(zg);
                    cout[gm*256 + q0] = cn;
                    hout[gm*256 + q0] = sigm(zo)*tanhf(cn);
                }
                {
                    float zi = acc[rh][1][ri][0]+a1.x, zf = acc[rh][1][ri][1]+a1.y;
                    float zg = acc[rh][1][ri][2]+a1.z, zo = acc[rh][1][ri][3]+a1.w;
                    float cold = first ? cB : cin[rmap[m]*256 + q1];
                    float cn = sigm(zf)*cold + sigm(zi)*tanhf(zg);
                    cout[gm*256 + q1] = cn;
                    hout[gm*256 + q1] = sigm(zo)*tanhf(cn);
                }
            }
    }
}

template<int MODE>
__global__ void __launch_bounds__(256)
gemm_small(const float* __restrict__ hin, float* __restrict__ hout,
           const float* __restrict__ cin, float* __restrict__ cout,
           const float* __restrict__ WT,
           const int* __restrict__ ids,
           const float* __restrict__ addbase,
           const float* __restrict__ c1,
           int first, int M)
{
    __shared__ float hs[16*264];
    __shared__ int rmap[16], aidx[16];
    int tid = threadIdx.x;
    int r = tid >> 4, tj = tid & 15;
    int m0 = blockIdx.x * 16;
    int j0q = blockIdx.y * 32;

    if (tid < 16){
        int gm = m0 + tid;
        int rr = 0, a = 0;
        if (gm < M){
            if (MODE == 0){ rr = gm; }
            else if (MODE == 1){ rr = gm; a = gm*4; }
            else if (MODE == 2){ rr = gm; a = ids[gm*4]; }
            else if (MODE == 3){ rr = gm/26; a = gm - rr*26; }
            else { int i0 = ids[gm*4], i1 = ids[gm*4+1]; a = ids[gm*4+2]; rr = i0*26 + i1; }
        }
        rmap[tid] = rr; aidx[tid] = a;
    }
    __syncthreads();
    #pragma unroll
    for (int q = 0; q < 4; q++){
        int e = tid + q*256;
        int row = e >> 6, c4 = e & 63;
        int gm = m0 + row;
        float4 v = make_float4(0.f,0.f,0.f,0.f);
        if (gm < M)
            v = (MODE != 0 && first) ? *reinterpret_cast<const float4*>(&hin[c4*4])
                                     : *reinterpret_cast<const float4*>(&hin[rmap[row]*256 + c4*4]);
        *reinterpret_cast<float4*>(&hs[row*264 + c4*4]) = v;
    }
    __syncthreads();

    int q0 = j0q + tj, q1 = j0q + tj + 16;
    float4 acc0 = make_float4(0.f,0.f,0.f,0.f);
    float4 acc1 = make_float4(0.f,0.f,0.f,0.f);
    const float* w0 = WT + q0*4;
    const float* w1 = WT + q1*4;
    #pragma unroll 4
    for (int k = 0; k < 256; k++){
        float a = hs[r*264 + k];
        float4 b0 = *reinterpret_cast<const float4*>(&w0[k*1024]);
        float4 b1 = *reinterpret_cast<const float4*>(&w1[k*1024]);
        acc0.x = fmaf(a,b0.x,acc0.x); acc0.y = fmaf(a,b0.y,acc0.y);
        acc0.z = fmaf(a,b0.z,acc0.z); acc0.w = fmaf(a,b0.w,acc0.w);
        acc1.x = fmaf(a,b1.x,acc1.x); acc1.y = fmaf(a,b1.y,acc1.y);
        acc1.z = fmaf(a,b1.z,acc1.z); acc1.w = fmaf(a,b1.w,acc1.w);
    }
    int gm = m0 + r;
    if (gm >= M) return;
    if (MODE == 0){
        float4 bz0 = *reinterpret_cast<const float4*>(&addbase[q0*4]);
        float4 bz1 = *reinterpret_cast<const float4*>(&addbase[q1*4]);
        *reinterpret_cast<float4*>(&hout[gm*1024 + q0*4]) =
            make_float4(acc0.x+bz0.x, acc0.y+bz0.y, acc0.z+bz0.z, acc0.w+bz0.w);
        *reinterpret_cast<float4*>(&hout[gm*1024 + q1*4]) =
            make_float4(acc1.x+bz1.x, acc1.y+bz1.y, acc1.z+bz1.z, acc1.w+bz1.w);
    } else {
        const float* ad = addbase + aidx[r]*1024;
        float4 a0 = *reinterpret_cast<const float4*>(&ad[q0*4]);
        float4 a1 = *reinterpret_cast<const float4*>(&ad[q1*4]);
        {
            float zi = acc0.x+a0.x, zf = acc0.y+a0.y, zg = acc0.z+a0.z, zo = acc0.w+a0.w;
            float cold = first ? c1[q0] : cin[rmap[r]*256 + q0];
            float cn = sigm(zf)*cold + sigm(zi)*tanhf(zg);
            cout[gm*256 + q0] = cn;
            hout[gm*256 + q0] = sigm(zo)*tanhf(cn);
        }
        {
            float zi = acc1.x+a1.x, zf = acc1.y+a1.y, zg = acc1.z+a1.z, zo = acc1.w+a1.w;
            float cold = first ? c1[q1] : cin[rmap[r]*256 + q1];
            float cn = sigm(zf)*cold + sigm(zi)*tanhf(zg);
            cout[gm*256 + q1] = cn;
            hout[gm*256 + q1] = sigm(zo)*tanhf(cn);
        }
    }
}

// ---------------- tag + log_softmax ----------------
__global__ void tag_kernel(const float* __restrict__ h, const int* __restrict__ ids,
                           float* __restrict__ out, int M)
{
    __shared__ float As[32][20];
    __shared__ float Ws[32][256];
    __shared__ float red[16][16];
    __shared__ float rowmax[16], rowlse[16];
    float* stag = &Ws[0][0];

    int tid = threadIdx.x;
    int rg = tid >> 6;
    int cg = tid & 63;
    int m0 = blockIdx.x * 16;

    float acc[4][4];
    #pragma unroll
    for (int a = 0; a < 4; a++)
        #pragma unroll
        for (int b = 0; b < 4; b++) acc[a][b] = 0.f;

    for (int k0 = 0; k0 < 256; k0 += 32){
        #pragma unroll
        for (int q = 0; q < 2; q++){
            int e = tid + q*256;
            int m = e >> 5, kk = e & 31;
            int gm = m0 + m;
            As[kk][m] = (gm < M) ? h[gm*256 + k0 + kk] : 0.f;
        }
        #pragma unroll
        for (int q = 0; q < 8; q++){
            int e = tid + q*256;
            int kk = e >> 6, c4 = e & 63;
            *reinterpret_cast<float4*>(&Ws[kk][c4*4]) =
                *reinterpret_cast<const float4*>(&g_WcombHT[(k0+kk)*256 + c4*4]);
        }
        __syncthreads();
        #pragma unroll
        for (int kk = 0; kk < 32; kk++){
            float4 a = *reinterpret_cast<const float4*>(&As[kk][rg*4]);
            float4 b = *reinterpret_cast<const float4*>(&Ws[kk][cg*4]);
            acc[0][0] = fmaf(a.x, b.x, acc[0][0]); acc[0][1] = fmaf(a.x, b.y, acc[0][1]);
            acc[0][2] = fmaf(a.x, b.z, acc[0][2]); acc[0][3] = fmaf(a.x, b.w, acc[0][3]);
            acc[1][0] = fmaf(a.y, b.x, acc[1][0]); acc[1][1] = fmaf(a.y, b.y, acc[1][1]);
            acc[1][2] = fmaf(a.y, b.z, acc[1][2]); acc[1][3] = fmaf(a.y, b.w, acc[1][3]);
            acc[2][0] = fmaf(a.z, b.x, acc[2][0]); acc[2][1] = fmaf(a.z, b.y, acc[2][1]);
            acc[2][2] = fmaf(a.z, b.z, acc[2][2]); acc[2][3] = fmaf(a.z, b.w, acc[2][3]);
            acc[3][0] = fmaf(a.w, b.x, acc[3][0]); acc[3][1] = fmaf(a.w, b.y, acc[3][1]);
            acc[3][2] = fmaf(a.w, b.z, acc[3][2]); acc[3][3] = fmaf(a.w, b.w, acc[3][3]);
        }
        __syncthreads();
    }

    float4 bc = *reinterpret_cast<const float4*>(&g_bcomb[cg*4]);
    #pragma unroll
    for (int ri = 0; ri < 4; ri++){
        int r = rg*4 + ri;
        int gm = m0 + r;
        int id = (gm < M) ? ids[gm] : 0;
        float4 te = *reinterpret_cast<const float4*>(&g_tagE[id*256 + cg*4]);
        float4 v = make_float4(acc[ri][0]+te.x+bc.x, acc[ri][1]+te.y+bc.y,
                               acc[ri][2]+te.z+bc.z, acc[ri][3]+te.w+bc.w);
        *reinterpret_cast<float4*>(&stag[r*256 + cg*4]) = v;
    }
    __syncthreads();
    {
        int r = tid >> 4, s = tid & 15;
        float mx = -1e30f;
        #pragma unroll
        for (int q = 0; q < 16; q++) mx = fmaxf(mx, stag[r*256 + s*16 + q]);
        red[r][s] = mx;
    }
    __syncthreads();
    if (tid < 16){
        float mx = red[tid][0];
        #pragma unroll
        for (int s = 1; s < 16; s++) mx = fmaxf(mx, red[tid][s]);
        rowmax[tid] = mx;
    }
    __syncthreads();
    {
        int r = tid >> 4, s = tid & 15;
        float sm = 0.f, mx = rowmax[r];
        #pragma unroll
        for (int q = 0; q < 16; q++) sm += expf(stag[r*256 + s*16 + q] - mx);
        red[r][s] = sm;
    }
    __syncthreads();
    if (tid < 16){
        float sm = 0.f;
        #pragma unroll
        for (int s = 0; s < 16; s++) sm += red[tid][s];
        rowlse[tid] = logf(sm);
    }
    __syncthreads();
    #pragma unroll
    for (int q = 0; q < 16; q++){
        int e = tid + q*256;
        int r = e >> 8, i = e & 255;
        int gm = m0 + r;
        if (gm < M) out[gm*256 + i] = stag[r*256 + i] - rowmax[r] - rowlse[r];
    }
}

// ---------------- host launcher ----------------
extern "C" void kernel_launch(void* const* d_in, const int* in_sizes, int n_in,
                              void* d_out, int out_size)
{
    const int*   idents    = (const int*)  d_in[0];
    const float* emb       = (const float*)d_in[1];
    const float* W_ih      = (const float*)d_in[2];
    const float* W_hh      = (const float*)d_in[3];
    const float* b_ih      = (const float*)d_in[4];
    const float* b_hh      = (const float*)d_in[5];
    const float* Wc        = (const float*)d_in[6];
    const float* bc        = (const float*)d_in[7];
    const float* Wt        = (const float*)d_in[8];
    const float* bt        = (const float*)d_in[9];
    const float* lstm_init = (const float*)d_in[10];
    float* out = (float*)d_out;
    (void)in_sizes; (void)n_in; (void)out_size;

    void* p;
    float *hA, *hB, *cbuf, *chA, *chB, *xw, *wcatT, *leafxW, *bzT, *h1, *c1;
    float *h26, *c26, *h676, *c676;
    cudaGetSymbolAddress(&p, g_hA);     hA     = (float*)p;
    cudaGetSymbolAddress(&p, g_hB);     hB     = (float*)p;
    cudaGetSymbolAddress(&p, g_c);      cbuf   = (float*)p;
    cudaGetSymbolAddress(&p, g_childA); chA    = (float*)p;
    cudaGetSymbolAddress(&p, g_childB); chB    = (float*)p;
    cudaGetSymbolAddress(&p, g_xw);     xw     = (float*)p;
    cudaGetSymbolAddress(&p, g_WcatT);  wcatT  = (float*)p;
    cudaGetSymbolAddress(&p, g_leafxW); leafxW = (float*)p;
    cudaGetSymbolAddress(&p, g_bzT);    bzT    = (float*)p;
    cudaGetSymbolAddress(&p, g_h1);     h1     = (float*)p;
    cudaGetSymbolAddress(&p, g_c1);     c1     = (float*)p;
    cudaGetSymbolAddress(&p, g_h26);    h26    = (float*)p;
    cudaGetSymbolAddress(&p, g_c26);    c26    = (float*)p;
    cudaGetSymbolAddress(&p, g_h676);   h676   = (float*)p;
    cudaGetSymbolAddress(&p, g_c676);   c676   = (float*)p;
    float* child[2] = { chA, chB };
    const float* whh = wcatT + 256*1024;
    const float* wih = wcatT;

    // prologue (tiny)
    k_init_h1c1<<<1, 1024>>>(W_ih, b_ih, b_hh, lstm_init);
    k_build_wcatT<<<2048, 256>>>(W_ih, W_hh);
    k_bzT<<<1, 1024>>>(b_ih, b_hh);
    k_wcomb<<<512, 256>>>(Wt, Wc);
    k_bcomb<<<1, 256>>>(Wt, bc, bt);
    k_wcombHT<<<256, 256>>>();
    k_tagE<<<26, 256>>>(emb);
    k_leafout<<<26, 256>>>();
    k_leafxw<<<104, 256>>>(W_ih, b_ih, b_hh);
    k_hh1<<<4, 256>>>();
    k_cell26<<<26, 256>>>();

    const int leaf_off = 21845;   // (4^8-1)/3
    // level 7 with state dedup
    {
        int M = 16384;
        const int off7 = 5461;    // (4^7-1)/3
        // child-step 1: 676 pair states
        gemm_small<3><<<dim3(43,8), 256>>>(h26, h676, c26, c676, whh,
                                           nullptr, leafxW, c1, 0, 676);
        // child-step 2: full nodes, gather triple state
        gemm_big<4><<<dim3(128,8), 256>>>(h676, hA, c676, cbuf, whh,
                                          idents + leaf_off, leafxW, c1, 0, M);
        // child-step 3
        gemm_big<2><<<dim3(128,8), 256>>>(hA, hB, cbuf, cbuf, whh,
                                          idents + leaf_off + 3, leafxW, c1, 0, M);
        tag_kernel<<<1024, 256>>>(hB, idents + off7, child[0], M);
    }

    // levels 6..0
    int cur = 0;
    for (int l = 6; l >= 0; l--){
        int M = 1 << (2*l);
        int M4 = 4*M;
        int off = (M - 1)/3;
        // xw = child @ W_ih^T + biases
        if (M4 >= 2048)
            gemm_big<0><<<dim3(M4/128, 8), 256>>>(child[cur], xw, nullptr, nullptr,
                                                  wih, nullptr, bzT, c1, 0, M4);
        else
            gemm_small<0><<<dim3((M4+15)/16, 8), 256>>>(child[cur], xw, nullptr, nullptr,
                                                        wih, nullptr, bzT, c1, 0, M4);
        // 4 recurrent steps
        for (int t = 0; t < 4; t++){
            const float* hin = (t == 0) ? h1 : ((t & 1) ? hA : hB);
            float* hout = (t & 1) ? hB : hA;
            if (M >= 2048)
                gemm_big<1><<<dim3(M/128, 8), 256>>>(hin, hout, cbuf, cbuf, whh,
                                                     nullptr, xw + t*1024, c1, (t==0)?1:0, M);
            else
                gemm_small<1><<<dim3((M+15)/16, 8), 256>>>(hin, hout, cbuf, cbuf, whh,
                                                           nullptr, xw + t*1024, c1, (t==0)?1:0, M);
        }
        float* o = (l == 0) ? out : child[cur ^ 1];
        tag_kernel<<<(M + 15)/16, 256>>>(hB, idents + off, o, M);
        cur ^= 1;
    }
}